// round 3
// baseline (speedup 1.0000x reference)
#include <cuda_runtime.h>
#include <math.h>

#define BATCH 2
#define TSEQ  2048
#define CDIM  1024
#define NHEAD 16
#define HD    64
#define MROWS (BATCH * TSEQ)     // 4096
#define NQKV  (3 * CDIM)         // 3072

// Scratch (allocation-free: __device__ globals)
__device__ float g_Q[BATCH * NHEAD * TSEQ * HD];
__device__ float g_K[BATCH * NHEAD * TSEQ * HD];
__device__ float g_V[BATCH * NHEAD * TSEQ * HD];
__device__ float g_O[MROWS * CDIM];

// ---------------------------------------------------------------------------
// SGEMM: C = A(MxK) * B(KxN) + bias, 128x128x8 tiles, 8x8 per thread.
// MODE 0: A = hidden, epilogue splits qkv, fake-quants K/V, scatters to
//         g_Q/g_K/g_V in [B,H,T,D] layout.
// MODE 1: A = g_O (ignores the A arg), epilogue writes Cout row-major.
// ---------------------------------------------------------------------------
template <int MODE>
__global__ __launch_bounds__(256) void sgemm_kernel(
    const float* __restrict__ A, const float* __restrict__ B,
    const float* __restrict__ bias, int K, int N,
    const float* __restrict__ scale_p, const float* __restrict__ zp_p,
    float* __restrict__ Cout)
{
    constexpr int BM = 128, BN = 128, BK = 8;
    __shared__ float As[BK][BM];
    __shared__ float Bs[BK][BN + 4];   // pad to soften LDS conflicts

    const float* Ap = (MODE == 0) ? A : g_O;

    const int tid = threadIdx.x;
    const int m0 = blockIdx.y * BM;
    const int n0 = blockIdx.x * BN;
    const int ty = tid >> 4;          // 0..15
    const int tx = tid & 15;          // 0..15

    float acc[8][8];
#pragma unroll
    for (int i = 0; i < 8; ++i)
#pragma unroll
        for (int j = 0; j < 8; ++j) acc[i][j] = 0.0f;

    // load mapping
    const int arow = tid >> 1;            // 0..127
    const int acol = (tid & 1) * 4;       // 0 or 4
    const int brow = tid >> 5;            // 0..7
    const int bcol = (tid & 31) * 4;      // 0..124

    const float* Aptr = Ap + (size_t)(m0 + arow) * K + acol;
    const float* Bptr = B + (size_t)brow * N + n0 + bcol;

    float4 aReg = *(const float4*)Aptr;
    float4 bReg = *(const float4*)Bptr;

    const int nk = K / BK;
    for (int kt = 0; kt < nk; ++kt) {
        As[acol + 0][arow] = aReg.x;
        As[acol + 1][arow] = aReg.y;
        As[acol + 2][arow] = aReg.z;
        As[acol + 3][arow] = aReg.w;
        *(float4*)&Bs[brow][bcol] = bReg;
        __syncthreads();

        if (kt + 1 < nk) {
            aReg = *(const float4*)(Aptr + (kt + 1) * BK);
            bReg = *(const float4*)(Bptr + (size_t)(kt + 1) * BK * N);
        }

#pragma unroll
        for (int kk = 0; kk < BK; ++kk) {
            float ra[8], rb[8];
            *(float4*)&ra[0] = *(const float4*)&As[kk][ty * 8 + 0];
            *(float4*)&ra[4] = *(const float4*)&As[kk][ty * 8 + 4];
            *(float4*)&rb[0] = *(const float4*)&Bs[kk][tx * 8 + 0];
            *(float4*)&rb[4] = *(const float4*)&Bs[kk][tx * 8 + 4];
#pragma unroll
            for (int i = 0; i < 8; ++i)
#pragma unroll
                for (int j = 0; j < 8; ++j) acc[i][j] += ra[i] * rb[j];
        }
        __syncthreads();
    }

    if (MODE == 0) {
        const float scale = *scale_p;
        const float zp = *zp_p;
#pragma unroll
        for (int i = 0; i < 8; ++i) {
            const int m = m0 + ty * 8 + i;
            const int bb = m >> 11;          // / 2048
            const int t = m & 2047;
#pragma unroll
            for (int j = 0; j < 8; ++j) {
                const int n = n0 + tx * 8 + j;
                float v = acc[i][j] + bias[n];
                const int which = n >> 10;   // 0=q 1=k 2=v
                const int c = n & 1023;
                const int h = c >> 6;
                const int d = c & 63;
                const int idx = (((bb * NHEAD + h) * TSEQ + t) * HD + d);
                if (which == 0) {
                    g_Q[idx] = v;
                } else {
                    float qv = v / scale + zp;
                    qv = rintf(qv);                       // half-to-even, matches jnp.round
                    qv = fminf(fmaxf(qv, 0.0f), 255.0f);
                    const float fq = (qv - zp) * scale;
                    if (which == 1) g_K[idx] = fq; else g_V[idx] = fq;
                }
            }
        }
    } else {
#pragma unroll
        for (int i = 0; i < 8; ++i) {
            const int m = m0 + ty * 8 + i;
#pragma unroll
            for (int j = 0; j < 8; ++j) {
                const int n = n0 + tx * 8 + j;
                Cout[(size_t)m * N + n] = acc[i][j] + bias[n];
            }
        }
    }
}

// ---------------------------------------------------------------------------
// Causal flash attention, fp32. 128 q-rows per block (1 per thread),
// K/V tiles of 64 keys in SMEM, online softmax in 16-key chunks.
// Output written in [B, T, C] layout for the proj GEMM.
// ---------------------------------------------------------------------------
__global__ __launch_bounds__(128, 2) void flash_kernel()
{
    __shared__ float Ks[64][64];
    __shared__ float Vs[64][64];

    const int qb = blockIdx.x;     // 0..15
    const int h  = blockIdx.y;     // 0..15
    const int b  = blockIdx.z;     // 0..1
    const int tid = threadIdx.x;
    const int qi = qb * 128 + tid;

    const size_t bh = (size_t)(b * NHEAD + h) * TSEQ * HD;
    const float* Qrow = g_Q + bh + (size_t)qi * HD;
    const float* Kbase = g_K + bh;
    const float* Vbase = g_V + bh;

    float q[64], o[64];
#pragma unroll
    for (int d4 = 0; d4 < 16; ++d4) {
        float4 v = ((const float4*)Qrow)[d4];
        q[4 * d4 + 0] = v.x; q[4 * d4 + 1] = v.y;
        q[4 * d4 + 2] = v.z; q[4 * d4 + 3] = v.w;
    }
#pragma unroll
    for (int d = 0; d < 64; ++d) o[d] = 0.0f;

    float mI = -INFINITY, lI = 0.0f;
    const int ntiles = 2 * qb + 2;   // keys 0 .. qb*128+127

    for (int j = 0; j < ntiles; ++j) {
        const float* Kt = Kbase + (size_t)j * 64 * HD;
        const float* Vt = Vbase + (size_t)j * 64 * HD;
#pragma unroll
        for (int it = 0; it < 8; ++it) {
            const int li = tid + it * 128;       // float4 index 0..1023
            const int r = li >> 4, cc = li & 15;
            ((float4*)&Ks[r][0])[cc] = ((const float4*)Kt)[li];
            ((float4*)&Vs[r][0])[cc] = ((const float4*)Vt)[li];
        }
        __syncthreads();

        const bool maskTile = (j >= 2 * qb);

        for (int c = 0; c < 4; ++c) {
            float s[16];
#pragma unroll
            for (int kk = 0; kk < 16; ++kk) {
                const float4* kr = (const float4*)&Ks[c * 16 + kk][0];
                float a0 = 0.f, a1 = 0.f, a2 = 0.f, a3 = 0.f;
#pragma unroll
                for (int d4 = 0; d4 < 16; ++d4) {
                    float4 kv = kr[d4];
                    a0 += q[4 * d4 + 0] * kv.x;
                    a1 += q[4 * d4 + 1] * kv.y;
                    a2 += q[4 * d4 + 2] * kv.z;
                    a3 += q[4 * d4 + 3] * kv.w;
                }
                float sv = ((a0 + a1) + (a2 + a3)) * 0.125f;  // 1/sqrt(64)
                if (maskTile) {
                    const int key = j * 64 + c * 16 + kk;
                    if (key > qi) sv = -INFINITY;
                }
                s[kk] = sv;
            }

            float mx = s[0];
#pragma unroll
            for (int kk = 1; kk < 16; ++kk) mx = fmaxf(mx, s[kk]);
            const float mNew = fmaxf(mI, mx);
            const float corr = __expf(mI - mNew);   // 0 on first chunk (mI=-inf)

            float p[16];
            float ps = 0.0f;
#pragma unroll
            for (int kk = 0; kk < 16; ++kk) {
                p[kk] = __expf(s[kk] - mNew);       // exp(-inf)=0 for masked
                ps += p[kk];
            }
            lI = lI * corr + ps;
            mI = mNew;

#pragma unroll
            for (int d = 0; d < 64; ++d) o[d] *= corr;
#pragma unroll
            for (int kk = 0; kk < 16; ++kk) {
                const float4* vr = (const float4*)&Vs[c * 16 + kk][0];
                const float pv = p[kk];
#pragma unroll
                for (int d4 = 0; d4 < 16; ++d4) {
                    float4 vv = vr[d4];
                    o[4 * d4 + 0] += pv * vv.x;
                    o[4 * d4 + 1] += pv * vv.y;
                    o[4 * d4 + 2] += pv * vv.z;
                    o[4 * d4 + 3] += pv * vv.w;
                }
            }
        }
        __syncthreads();
    }

    const float inv = 1.0f / lI;
    float* Or = g_O + (size_t)(b * TSEQ + qi) * CDIM + h * HD;
#pragma unroll
    for (int d4 = 0; d4 < 16; ++d4) {
        float4 vv;
        vv.x = o[4 * d4 + 0] * inv;
        vv.y = o[4 * d4 + 1] * inv;
        vv.z = o[4 * d4 + 2] * inv;
        vv.w = o[4 * d4 + 3] * inv;
        ((float4*)Or)[d4] = vv;
    }
}

// ---------------------------------------------------------------------------
// Launch
// inputs: 0 hidden_states [2,2048,1024] f32
//         1 W_attn [1024,3072] f32
//         2 b_attn [3072] f32
//         3 W_proj [1024,1024] f32
//         4 b_proj [1024] f32
//         5 kv_scale [1] f32
//         6 kv_zp [1] f32
// output: [2,2048,1024] f32
// ---------------------------------------------------------------------------
extern "C" void kernel_launch(void* const* d_in, const int* in_sizes, int n_in,
                              void* d_out, int out_size)
{
    const float* hidden  = (const float*)d_in[0];
    const float* W_attn  = (const float*)d_in[1];
    const float* b_attn  = (const float*)d_in[2];
    const float* W_proj  = (const float*)d_in[3];
    const float* b_proj  = (const float*)d_in[4];
    const float* kv_scale = (const float*)d_in[5];
    const float* kv_zp    = (const float*)d_in[6];
    float* out = (float*)d_out;

    // QKV GEMM + bias + fake-quant + scatter
    {
        dim3 grid(NQKV / 128, MROWS / 128);     // (24, 32)
        sgemm_kernel<0><<<grid, 256>>>(hidden, W_attn, b_attn, CDIM, NQKV,
                                       kv_scale, kv_zp, nullptr);
    }
    // Causal flash attention
    {
        dim3 grid(TSEQ / 128, NHEAD, BATCH);    // (16, 16, 2)
        flash_kernel<<<grid, 128>>>();
    }
    // Output projection
    {
        dim3 grid(CDIM / 128, MROWS / 128);     // (8, 32)
        sgemm_kernel<1><<<grid, 256>>>(nullptr, W_proj, b_proj, CDIM, CDIM,
                                       nullptr, nullptr, out);
    }
}

// round 8
// speedup vs baseline: 1.4815x; 1.4815x over previous
#include <cuda_runtime.h>
#include <cuda_bf16.h>
#include <math.h>
#include <stdint.h>

#define BATCH 2
#define TSEQ  2048
#define CDIM  1024
#define NHEAD 16
#define HD    64
#define MROWS (BATCH * TSEQ)     // 4096
#define NQKV  (3 * CDIM)         // 3072
#define KDIM  1024

// ---------------------------------------------------------------------------
// Scratch (allocation-free: __device__ globals)
// ---------------------------------------------------------------------------
__device__ __align__(256) float g_Q[BATCH * NHEAD * TSEQ * HD];
__device__ __align__(256) float g_K[BATCH * NHEAD * TSEQ * HD];
__device__ __align__(256) float g_V[BATCH * NHEAD * TSEQ * HD];
__device__ __align__(256) __nv_bfloat16 g_Xhi[MROWS * CDIM];
__device__ __align__(256) __nv_bfloat16 g_Xlo[MROWS * CDIM];
__device__ __align__(256) __nv_bfloat16 g_WaThi[NQKV * CDIM];
__device__ __align__(256) __nv_bfloat16 g_WaTlo[NQKV * CDIM];
__device__ __align__(256) __nv_bfloat16 g_WpThi[CDIM * CDIM];
__device__ __align__(256) __nv_bfloat16 g_WpTlo[CDIM * CDIM];
__device__ __align__(256) __nv_bfloat16 g_Ohi[MROWS * CDIM];
__device__ __align__(256) __nv_bfloat16 g_Olo[MROWS * CDIM];

// ---------------------------------------------------------------------------
// PTX helpers (arch-generic only: cp.async, ldmatrix, mma.sync)
// ---------------------------------------------------------------------------
__device__ __forceinline__ uint32_t smem_u32(const void* p) {
    uint32_t a;
    asm("{ .reg .u64 t; cvta.to.shared.u64 t, %1; cvt.u32.u64 %0, t; }"
        : "=r"(a) : "l"(p));
    return a;
}

#define CPA16(dst, src) \
    asm volatile("cp.async.cg.shared.global [%0], [%1], 16;" :: "r"(dst), "l"(src))
#define CPA_COMMIT() asm volatile("cp.async.commit_group;" ::: "memory")
#define CPA_WAIT2()  asm volatile("cp.async.wait_group 2;" ::: "memory")
#define CPA_WAIT1()  asm volatile("cp.async.wait_group 1;" ::: "memory")
#define CPA_WAIT0()  asm volatile("cp.async.wait_group 0;" ::: "memory")

#define LDSM4(r, addr)                                                        \
    asm volatile("ldmatrix.sync.aligned.m8n8.x4.shared.b16 {%0,%1,%2,%3}, [%4];" \
        : "=r"((r)[0]), "=r"((r)[1]), "=r"((r)[2]), "=r"((r)[3]) : "r"(addr))

#define MMA_BF16(d, a, b0v, b1v)                                              \
    asm volatile("mma.sync.aligned.m16n8k16.row.col.f32.bf16.bf16.f32 "       \
        "{%0,%1,%2,%3}, {%4,%5,%6,%7}, {%8,%9}, {%0,%1,%2,%3};"               \
        : "+f"((d)[0]), "+f"((d)[1]), "+f"((d)[2]), "+f"((d)[3])              \
        : "r"((a)[0]), "r"((a)[1]), "r"((a)[2]), "r"((a)[3]),                 \
          "r"(b0v), "r"(b1v))

// ---------------------------------------------------------------------------
// Prep kernels: bf16 hi/lo split (+ transpose for weights so both GEMM
// operands are K-contiguous)
// ---------------------------------------------------------------------------
__global__ void split_kernel(const float* __restrict__ in,
                             __nv_bfloat16* __restrict__ hi,
                             __nv_bfloat16* __restrict__ lo, int n4) {
    for (int i = blockIdx.x * blockDim.x + threadIdx.x; i < n4;
         i += gridDim.x * blockDim.x) {
        float4 v = ((const float4*)in)[i];
        __nv_bfloat16 hx = __float2bfloat16_rn(v.x);
        __nv_bfloat16 hy = __float2bfloat16_rn(v.y);
        __nv_bfloat16 hz = __float2bfloat16_rn(v.z);
        __nv_bfloat16 hw = __float2bfloat16_rn(v.w);
        __nv_bfloat16 lx = __float2bfloat16_rn(v.x - __bfloat162float(hx));
        __nv_bfloat16 ly = __float2bfloat16_rn(v.y - __bfloat162float(hy));
        __nv_bfloat16 lz = __float2bfloat16_rn(v.z - __bfloat162float(hz));
        __nv_bfloat16 lw = __float2bfloat16_rn(v.w - __bfloat162float(hw));
        ((__nv_bfloat162*)hi)[2 * i + 0] = __nv_bfloat162(hx, hy);
        ((__nv_bfloat162*)hi)[2 * i + 1] = __nv_bfloat162(hz, hw);
        ((__nv_bfloat162*)lo)[2 * i + 0] = __nv_bfloat162(lx, ly);
        ((__nv_bfloat162*)lo)[2 * i + 1] = __nv_bfloat162(lz, lw);
    }
}

__global__ void transpose_split_kernel(const float* __restrict__ in,
                                       __nv_bfloat16* __restrict__ ohi,
                                       __nv_bfloat16* __restrict__ olo,
                                       int R, int C) {
    __shared__ float t[32][33];
    const int c0 = blockIdx.x * 32, r0 = blockIdx.y * 32;
    const int x = threadIdx.x & 31, y0 = threadIdx.x >> 5;
#pragma unroll
    for (int i = 0; i < 4; ++i) {
        int y = y0 + i * 8;
        t[y][x] = in[(size_t)(r0 + y) * C + c0 + x];
    }
    __syncthreads();
#pragma unroll
    for (int i = 0; i < 4; ++i) {
        int yy = y0 + i * 8;
        float v = t[x][yy];
        __nv_bfloat16 hi = __float2bfloat16_rn(v);
        __nv_bfloat16 lo = __float2bfloat16_rn(v - __bfloat162float(hi));
        size_t o = (size_t)(c0 + yy) * R + r0 + x;
        ohi[o] = hi;
        olo[o] = lo;
    }
}

// ---------------------------------------------------------------------------
// mma.sync bf16 split-3 GEMM: C(4096 x N) = A(4096x1024) * B^T(Nx1024) + bias
// CTA 128x128, 8 warps (warp tile 32x64), BK=32, 4-stage cp.async pipeline.
// MODE 0: epilogue fake-quant + scatter to g_Q/g_K/g_V.
// MODE 1: epilogue writes Cout row-major.
// ---------------------------------------------------------------------------
#define STAGE_BYTES 32768        // Ahi 8K | Alo 8K | Bhi 8K | Blo 8K
#define NSTAGES 4
#define SMEM_DYN (STAGE_BYTES * NSTAGES)   // 131072

template <int MODE>
__global__ __launch_bounds__(256, 1) void mma_gemm_kernel(
    const __nv_bfloat16* __restrict__ Ahi, const __nv_bfloat16* __restrict__ Alo,
    const __nv_bfloat16* __restrict__ Bhi, const __nv_bfloat16* __restrict__ Blo,
    const float* __restrict__ bias, int Ncols,
    const float* __restrict__ scale_p, const float* __restrict__ zp_p,
    float* __restrict__ Cout)
{
    extern __shared__ __align__(1024) char smem[];
    const uint32_t sb = smem_u32(smem);
    const int tid = threadIdx.x;
    const int wid = tid >> 5, lane = tid & 31;
    const int m0 = blockIdx.y * 128, n0 = blockIdx.x * 128;
    const int wm = wid & 3;       // warp row 0..3 (m += wm*32)
    const int wn = wid >> 2;      // warp col 0..1 (n += wn*64)

    float acc[2][8][4];
#pragma unroll
    for (int i = 0; i < 2; ++i)
#pragma unroll
        for (int j = 0; j < 8; ++j)
#pragma unroll
            for (int k = 0; k < 4; ++k) acc[i][j][k] = 0.0f;

    // XOR swizzle: 16B-unit column c' = c ^ ((row>>1)&3), rows of 64B.
    auto load_stage = [&](int kt, int s) {
        const uint32_t st = sb + (uint32_t)s * STAGE_BYTES;
        const int kb = kt * 32;
#pragma unroll
        for (int p = 0; p < 2; ++p) {
            const __nv_bfloat16* src = p ? Alo : Ahi;
            const uint32_t po = st + p * 8192;
#pragma unroll
            for (int i = 0; i < 2; ++i) {
                int idx = tid + i * 256;
                int row = idx >> 2, c = idx & 3;
                uint32_t dst = po + row * 64 + ((c ^ ((row >> 1) & 3)) << 4);
                CPA16(dst, src + (size_t)(m0 + row) * KDIM + kb + c * 8);
            }
        }
#pragma unroll
        for (int p = 0; p < 2; ++p) {
            const __nv_bfloat16* src = p ? Blo : Bhi;
            const uint32_t po = st + 16384 + p * 8192;
#pragma unroll
            for (int i = 0; i < 2; ++i) {
                int idx = tid + i * 256;
                int row = idx >> 2, c = idx & 3;
                uint32_t dst = po + row * 64 + ((c ^ ((row >> 1) & 3)) << 4);
                CPA16(dst, src + (size_t)(n0 + row) * KDIM + kb + c * 8);
            }
        }
        CPA_COMMIT();
    };

    load_stage(0, 0);
    load_stage(1, 1);
    load_stage(2, 2);

    const int NK = KDIM / 32;   // 32
    for (int kt = 0; kt < NK; ++kt) {
        const int s = kt & (NSTAGES - 1);
        if (kt <= NK - 3)      { CPA_WAIT2(); }
        else if (kt == NK - 2) { CPA_WAIT1(); }
        else                   { CPA_WAIT0(); }
        __syncthreads();

        const uint32_t st = sb + (uint32_t)s * STAGE_BYTES;
#pragma unroll
        for (int kh = 0; kh < 2; ++kh) {        // two k16 halves of BK=32
            const int cbase = kh * 2;
            uint32_t a[2][2][4];                // [plane][mfrag][4]
#pragma unroll
            for (int p = 0; p < 2; ++p) {
#pragma unroll
                for (int mf = 0; mf < 2; ++mf) {
                    int row = wm * 32 + mf * 16 + ((lane >> 3) & 1) * 8 + (lane & 7);
                    int c = cbase + ((lane >> 4) & 1);
                    uint32_t addr = st + p * 8192 + row * 64
                                  + ((c ^ ((row >> 1) & 3)) << 4);
                    LDSM4(a[p][mf], addr);
                }
            }
            uint32_t b[2][16];                  // [plane][nq*4 + ...]
#pragma unroll
            for (int p = 0; p < 2; ++p) {
#pragma unroll
                for (int nq = 0; nq < 4; ++nq) {
                    int row = wn * 64 + nq * 16 + ((lane >> 4) & 1) * 8 + (lane & 7);
                    int c = cbase + ((lane >> 3) & 1);
                    uint32_t addr = st + 16384 + p * 8192 + row * 64
                                  + ((c ^ ((row >> 1) & 3)) << 4);
                    LDSM4(&b[p][nq * 4], addr);
                }
            }
#pragma unroll
            for (int mf = 0; mf < 2; ++mf) {
#pragma unroll
                for (int nf = 0; nf < 8; ++nf) {
                    const int bi = (nf >> 1) * 4 + (nf & 1) * 2;
                    MMA_BF16(acc[mf][nf], a[0][mf], b[0][bi], b[0][bi + 1]); // hi*hi
                    MMA_BF16(acc[mf][nf], a[1][mf], b[0][bi], b[0][bi + 1]); // lo*hi
                    MMA_BF16(acc[mf][nf], a[0][mf], b[1][bi], b[1][bi + 1]); // hi*lo
                }
            }
        }

        if (kt + 3 < NK) load_stage(kt + 3, (kt + 3) & (NSTAGES - 1));
    }

    // ---- epilogue ----
    float scl = 1.0f, zp = 0.0f;
    if (MODE == 0) { scl = *scale_p; zp = *zp_p; }

#pragma unroll
    for (int mf = 0; mf < 2; ++mf) {
#pragma unroll
        for (int nf = 0; nf < 8; ++nf) {
            const int n = n0 + wn * 64 + nf * 8 + (lane & 3) * 2;
            const float2 bv = *(const float2*)(bias + n);
#pragma unroll
            for (int half = 0; half < 2; ++half) {
                const int m = m0 + wm * 32 + mf * 16 + (lane >> 2) + half * 8;
                float v0 = acc[mf][nf][half * 2 + 0] + bv.x;
                float v1 = acc[mf][nf][half * 2 + 1] + bv.y;
                if (MODE == 0) {
                    const int bb = m >> 11;
                    const int t = m & 2047;
                    const int which = n >> 10;
                    const int cI = n & 1023;
                    const int h = cI >> 6, d = cI & 63;
                    const size_t idx = (((size_t)(bb * NHEAD + h) * TSEQ + t) * HD + d);
                    if (which == 0) {
                        *(float2*)(g_Q + idx) = make_float2(v0, v1);
                    } else {
                        float q0 = fminf(fmaxf(rintf(v0 / scl + zp), 0.0f), 255.0f);
                        float q1 = fminf(fmaxf(rintf(v1 / scl + zp), 0.0f), 255.0f);
                        float2 fq = make_float2((q0 - zp) * scl, (q1 - zp) * scl);
                        if (which == 1) *(float2*)(g_K + idx) = fq;
                        else            *(float2*)(g_V + idx) = fq;
                    }
                } else {
                    *(float2*)(Cout + (size_t)m * Ncols + n) = make_float2(v0, v1);
                }
            }
        }
    }
}

// ---------------------------------------------------------------------------
// Causal flash attention, fp32 (proven in R3). qb reversed so the longest
// causal blocks launch first. Epilogue emits bf16 hi/lo for the proj GEMM.
// ---------------------------------------------------------------------------
__global__ __launch_bounds__(128, 2) void flash_kernel()
{
    __shared__ float Ks[64][64];
    __shared__ float Vs[64][64];

    const int qb = (TSEQ / 128 - 1) - blockIdx.x;   // long blocks first
    const int h  = blockIdx.y;
    const int b  = blockIdx.z;
    const int tid = threadIdx.x;
    const int qi = qb * 128 + tid;

    const size_t bh = (size_t)(b * NHEAD + h) * TSEQ * HD;
    const float* Qrow = g_Q + bh + (size_t)qi * HD;
    const float* Kbase = g_K + bh;
    const float* Vbase = g_V + bh;

    float q[64], o[64];
#pragma unroll
    for (int d4 = 0; d4 < 16; ++d4) {
        float4 v = ((const float4*)Qrow)[d4];
        q[4 * d4 + 0] = v.x; q[4 * d4 + 1] = v.y;
        q[4 * d4 + 2] = v.z; q[4 * d4 + 3] = v.w;
    }
#pragma unroll
    for (int d = 0; d < 64; ++d) o[d] = 0.0f;

    float mI = -INFINITY, lI = 0.0f;
    const int ntiles = 2 * qb + 2;

    for (int j = 0; j < ntiles; ++j) {
        const float* Kt = Kbase + (size_t)j * 64 * HD;
        const float* Vt = Vbase + (size_t)j * 64 * HD;
#pragma unroll
        for (int it = 0; it < 8; ++it) {
            const int li = tid + it * 128;
            const int r = li >> 4, cc = li & 15;
            ((float4*)&Ks[r][0])[cc] = ((const float4*)Kt)[li];
            ((float4*)&Vs[r][0])[cc] = ((const float4*)Vt)[li];
        }
        __syncthreads();

        const bool maskTile = (j >= 2 * qb);

        for (int c = 0; c < 4; ++c) {
            float s[16];
#pragma unroll
            for (int kk = 0; kk < 16; ++kk) {
                const float4* kr = (const float4*)&Ks[c * 16 + kk][0];
                float a0 = 0.f, a1 = 0.f, a2 = 0.f, a3 = 0.f;
#pragma unroll
                for (int d4 = 0; d4 < 16; ++d4) {
                    float4 kv = kr[d4];
                    a0 += q[4 * d4 + 0] * kv.x;
                    a1 += q[4 * d4 + 1] * kv.y;
                    a2 += q[4 * d4 + 2] * kv.z;
                    a3 += q[4 * d4 + 3] * kv.w;
                }
                float sv = ((a0 + a1) + (a2 + a3)) * 0.125f;
                if (maskTile) {
                    const int key = j * 64 + c * 16 + kk;
                    if (key > qi) sv = -INFINITY;
                }
                s[kk] = sv;
            }

            float mx = s[0];
#pragma unroll
            for (int kk = 1; kk < 16; ++kk) mx = fmaxf(mx, s[kk]);
            const float mNew = fmaxf(mI, mx);
            const float corr = __expf(mI - mNew);

            float p[16];
            float ps = 0.0f;
#pragma unroll
            for (int kk = 0; kk < 16; ++kk) {
                p[kk] = __expf(s[kk] - mNew);
                ps += p[kk];
            }
            lI = lI * corr + ps;
            mI = mNew;

#pragma unroll
            for (int d = 0; d < 64; ++d) o[d] *= corr;
#pragma unroll
            for (int kk = 0; kk < 16; ++kk) {
                const float4* vr = (const float4*)&Vs[c * 16 + kk][0];
                const float pv = p[kk];
#pragma unroll
                for (int d4 = 0; d4 < 16; ++d4) {
                    float4 vv = vr[d4];
                    o[4 * d4 + 0] += pv * vv.x;
                    o[4 * d4 + 1] += pv * vv.y;
                    o[4 * d4 + 2] += pv * vv.z;
                    o[4 * d4 + 3] += pv * vv.w;
                }
            }
        }
        __syncthreads();
    }

    const float inv = 1.0f / lI;
    const size_t ob = (size_t)(b * TSEQ + qi) * CDIM + h * HD;
#pragma unroll
    for (int d4 = 0; d4 < 16; ++d4) {
        float v0 = o[4 * d4 + 0] * inv;
        float v1 = o[4 * d4 + 1] * inv;
        float v2 = o[4 * d4 + 2] * inv;
        float v3 = o[4 * d4 + 3] * inv;
        __nv_bfloat16 h0 = __float2bfloat16_rn(v0);
        __nv_bfloat16 h1 = __float2bfloat16_rn(v1);
        __nv_bfloat16 h2 = __float2bfloat16_rn(v2);
        __nv_bfloat16 h3 = __float2bfloat16_rn(v3);
        __nv_bfloat16 l0 = __float2bfloat16_rn(v0 - __bfloat162float(h0));
        __nv_bfloat16 l1 = __float2bfloat16_rn(v1 - __bfloat162float(h1));
        __nv_bfloat16 l2 = __float2bfloat16_rn(v2 - __bfloat162float(h2));
        __nv_bfloat16 l3 = __float2bfloat16_rn(v3 - __bfloat162float(h3));
        ((__nv_bfloat162*)(g_Ohi + ob))[2 * d4 + 0] = __nv_bfloat162(h0, h1);
        ((__nv_bfloat162*)(g_Ohi + ob))[2 * d4 + 1] = __nv_bfloat162(h2, h3);
        ((__nv_bfloat162*)(g_Olo + ob))[2 * d4 + 0] = __nv_bfloat162(l0, l1);
        ((__nv_bfloat162*)(g_Olo + ob))[2 * d4 + 1] = __nv_bfloat162(l2, l3);
    }
}

// ---------------------------------------------------------------------------
// Launch
// ---------------------------------------------------------------------------
extern "C" void kernel_launch(void* const* d_in, const int* in_sizes, int n_in,
                              void* d_out, int out_size)
{
    const float* hidden   = (const float*)d_in[0];
    const float* W_attn   = (const float*)d_in[1];
    const float* b_attn   = (const float*)d_in[2];
    const float* W_proj   = (const float*)d_in[3];
    const float* b_proj   = (const float*)d_in[4];
    const float* kv_scale = (const float*)d_in[5];
    const float* kv_zp    = (const float*)d_in[6];
    float* out = (float*)d_out;

    cudaFuncSetAttribute(mma_gemm_kernel<0>,
                         cudaFuncAttributeMaxDynamicSharedMemorySize, SMEM_DYN);
    cudaFuncSetAttribute(mma_gemm_kernel<1>,
                         cudaFuncAttributeMaxDynamicSharedMemorySize, SMEM_DYN);

    __nv_bfloat16 *Xhi, *Xlo, *WaThi, *WaTlo, *WpThi, *WpTlo, *Ohi, *Olo;
    cudaGetSymbolAddress((void**)&Xhi, g_Xhi);
    cudaGetSymbolAddress((void**)&Xlo, g_Xlo);
    cudaGetSymbolAddress((void**)&WaThi, g_WaThi);
    cudaGetSymbolAddress((void**)&WaTlo, g_WaTlo);
    cudaGetSymbolAddress((void**)&WpThi, g_WpThi);
    cudaGetSymbolAddress((void**)&WpTlo, g_WpTlo);
    cudaGetSymbolAddress((void**)&Ohi, g_Ohi);
    cudaGetSymbolAddress((void**)&Olo, g_Olo);

    // Prep: bf16 hi/lo split of activations; transpose+split weights
    split_kernel<<<1024, 256>>>(hidden, Xhi, Xlo, MROWS * CDIM / 4);
    transpose_split_kernel<<<dim3(NQKV / 32, CDIM / 32), 256>>>(W_attn, WaThi, WaTlo, CDIM, NQKV);
    transpose_split_kernel<<<dim3(CDIM / 32, CDIM / 32), 256>>>(W_proj, WpThi, WpTlo, CDIM, CDIM);

    // QKV GEMM (bf16 split-3 mma.sync) + bias + fake-quant + scatter
    mma_gemm_kernel<0><<<dim3(NQKV / 128, MROWS / 128), 256, SMEM_DYN>>>(
        Xhi, Xlo, WaThi, WaTlo, b_attn, NQKV, kv_scale, kv_zp, nullptr);

    // Causal flash attention
    flash_kernel<<<dim3(TSEQ / 128, NHEAD, BATCH), 128>>>();

    // Output projection (bf16 split-3 mma.sync)
    mma_gemm_kernel<1><<<dim3(CDIM / 128, MROWS / 128), 256, SMEM_DYN>>>(
        Ohi, Olo, WpThi, WpTlo, b_proj, CDIM, nullptr, nullptr, out);
}

// round 9
// speedup vs baseline: 3.4336x; 2.3176x over previous
#include <cuda_runtime.h>
#include <cuda_bf16.h>
#include <math.h>
#include <stdint.h>

#define BATCH 2
#define TSEQ  2048
#define CDIM  1024
#define NHEAD 16
#define HD    64
#define MROWS (BATCH * TSEQ)     // 4096
#define NQKV  (3 * CDIM)         // 3072
#define KDIM  1024

// ---------------------------------------------------------------------------
// Scratch (allocation-free: __device__ globals). Q/K/V as bf16 hi/lo planes.
// ---------------------------------------------------------------------------
#define QKV_ELEMS (BATCH * NHEAD * TSEQ * HD)
__device__ __align__(256) __nv_bfloat16 g_Qhi[QKV_ELEMS];
__device__ __align__(256) __nv_bfloat16 g_Qlo[QKV_ELEMS];
__device__ __align__(256) __nv_bfloat16 g_Khi[QKV_ELEMS];
__device__ __align__(256) __nv_bfloat16 g_Klo[QKV_ELEMS];
__device__ __align__(256) __nv_bfloat16 g_Vhi[QKV_ELEMS];
__device__ __align__(256) __nv_bfloat16 g_Vlo[QKV_ELEMS];
__device__ __align__(256) __nv_bfloat16 g_Xhi[MROWS * CDIM];
__device__ __align__(256) __nv_bfloat16 g_Xlo[MROWS * CDIM];
__device__ __align__(256) __nv_bfloat16 g_WaThi[NQKV * CDIM];
__device__ __align__(256) __nv_bfloat16 g_WaTlo[NQKV * CDIM];
__device__ __align__(256) __nv_bfloat16 g_WpThi[CDIM * CDIM];
__device__ __align__(256) __nv_bfloat16 g_WpTlo[CDIM * CDIM];
__device__ __align__(256) __nv_bfloat16 g_Ohi[MROWS * CDIM];
__device__ __align__(256) __nv_bfloat16 g_Olo[MROWS * CDIM];

// ---------------------------------------------------------------------------
// PTX helpers (arch-generic only: cp.async, ldmatrix, mma.sync)
// ---------------------------------------------------------------------------
__device__ __forceinline__ uint32_t smem_u32(const void* p) {
    uint32_t a;
    asm("{ .reg .u64 t; cvta.to.shared.u64 t, %1; cvt.u32.u64 %0, t; }"
        : "=r"(a) : "l"(p));
    return a;
}

#define CPA16(dst, src) \
    asm volatile("cp.async.cg.shared.global [%0], [%1], 16;" :: "r"(dst), "l"(src))
#define CPA_COMMIT() asm volatile("cp.async.commit_group;" ::: "memory")
#define CPA_WAIT2()  asm volatile("cp.async.wait_group 2;" ::: "memory")
#define CPA_WAIT1()  asm volatile("cp.async.wait_group 1;" ::: "memory")
#define CPA_WAIT0()  asm volatile("cp.async.wait_group 0;" ::: "memory")

#define LDSM4(r, addr)                                                        \
    asm volatile("ldmatrix.sync.aligned.m8n8.x4.shared.b16 {%0,%1,%2,%3}, [%4];" \
        : "=r"((r)[0]), "=r"((r)[1]), "=r"((r)[2]), "=r"((r)[3]) : "r"(addr))

#define LDSM4T(r, addr)                                                       \
    asm volatile("ldmatrix.sync.aligned.m8n8.x4.trans.shared.b16 {%0,%1,%2,%3}, [%4];" \
        : "=r"((r)[0]), "=r"((r)[1]), "=r"((r)[2]), "=r"((r)[3]) : "r"(addr))

#define MMA_BF16(d, a, b0v, b1v)                                              \
    asm volatile("mma.sync.aligned.m16n8k16.row.col.f32.bf16.bf16.f32 "       \
        "{%0,%1,%2,%3}, {%4,%5,%6,%7}, {%8,%9}, {%0,%1,%2,%3};"               \
        : "+f"((d)[0]), "+f"((d)[1]), "+f"((d)[2]), "+f"((d)[3])              \
        : "r"((a)[0]), "r"((a)[1]), "r"((a)[2]), "r"((a)[3]),                 \
          "r"(b0v), "r"(b1v))

__device__ __forceinline__ uint32_t pack_bf2(float x, float y) {
    __nv_bfloat162 h = __floats2bfloat162_rn(x, y);
    return *(uint32_t*)&h;
}

// ---------------------------------------------------------------------------
// Prep kernels
// ---------------------------------------------------------------------------
__global__ void split_kernel(const float* __restrict__ in,
                             __nv_bfloat16* __restrict__ hi,
                             __nv_bfloat16* __restrict__ lo, int n4) {
    for (int i = blockIdx.x * blockDim.x + threadIdx.x; i < n4;
         i += gridDim.x * blockDim.x) {
        float4 v = ((const float4*)in)[i];
        __nv_bfloat16 hx = __float2bfloat16_rn(v.x);
        __nv_bfloat16 hy = __float2bfloat16_rn(v.y);
        __nv_bfloat16 hz = __float2bfloat16_rn(v.z);
        __nv_bfloat16 hw = __float2bfloat16_rn(v.w);
        __nv_bfloat16 lx = __float2bfloat16_rn(v.x - __bfloat162float(hx));
        __nv_bfloat16 ly = __float2bfloat16_rn(v.y - __bfloat162float(hy));
        __nv_bfloat16 lz = __float2bfloat16_rn(v.z - __bfloat162float(hz));
        __nv_bfloat16 lw = __float2bfloat16_rn(v.w - __bfloat162float(hw));
        ((__nv_bfloat162*)hi)[2 * i + 0] = __nv_bfloat162(hx, hy);
        ((__nv_bfloat162*)hi)[2 * i + 1] = __nv_bfloat162(hz, hw);
        ((__nv_bfloat162*)lo)[2 * i + 0] = __nv_bfloat162(lx, ly);
        ((__nv_bfloat162*)lo)[2 * i + 1] = __nv_bfloat162(lz, lw);
    }
}

__global__ void transpose_split_kernel(const float* __restrict__ in,
                                       __nv_bfloat16* __restrict__ ohi,
                                       __nv_bfloat16* __restrict__ olo,
                                       int R, int C) {
    __shared__ float t[32][33];
    const int c0 = blockIdx.x * 32, r0 = blockIdx.y * 32;
    const int x = threadIdx.x & 31, y0 = threadIdx.x >> 5;
#pragma unroll
    for (int i = 0; i < 4; ++i) {
        int y = y0 + i * 8;
        t[y][x] = in[(size_t)(r0 + y) * C + c0 + x];
    }
    __syncthreads();
#pragma unroll
    for (int i = 0; i < 4; ++i) {
        int yy = y0 + i * 8;
        float v = t[x][yy];
        __nv_bfloat16 hi = __float2bfloat16_rn(v);
        __nv_bfloat16 lo = __float2bfloat16_rn(v - __bfloat162float(hi));
        size_t o = (size_t)(c0 + yy) * R + r0 + x;
        ohi[o] = hi;
        olo[o] = lo;
    }
}

// ---------------------------------------------------------------------------
// mma.sync bf16 split-3 GEMM (proven in R8). CTA 128x128, 8 warps, BK=32.
// MODE 0: fake-quant + scatter to bf16 hi/lo Q/K/V planes.
// MODE 1: epilogue writes Cout row-major fp32.
// ---------------------------------------------------------------------------
#define STAGE_BYTES 32768        // Ahi 8K | Alo 8K | Bhi 8K | Blo 8K
#define NSTAGES 4
#define SMEM_DYN (STAGE_BYTES * NSTAGES)   // 131072

template <int MODE>
__global__ __launch_bounds__(256, 1) void mma_gemm_kernel(
    const __nv_bfloat16* __restrict__ Ahi, const __nv_bfloat16* __restrict__ Alo,
    const __nv_bfloat16* __restrict__ Bhi, const __nv_bfloat16* __restrict__ Blo,
    const float* __restrict__ bias, int Ncols,
    const float* __restrict__ scale_p, const float* __restrict__ zp_p,
    float* __restrict__ Cout)
{
    extern __shared__ __align__(1024) char smem[];
    const uint32_t sb = smem_u32(smem);
    const int tid = threadIdx.x;
    const int wid = tid >> 5, lane = tid & 31;
    const int m0 = blockIdx.y * 128, n0 = blockIdx.x * 128;
    const int wm = wid & 3;
    const int wn = wid >> 2;

    float acc[2][8][4];
#pragma unroll
    for (int i = 0; i < 2; ++i)
#pragma unroll
        for (int j = 0; j < 8; ++j)
#pragma unroll
            for (int k = 0; k < 4; ++k) acc[i][j][k] = 0.0f;

    auto load_stage = [&](int kt, int s) {
        const uint32_t st = sb + (uint32_t)s * STAGE_BYTES;
        const int kb = kt * 32;
#pragma unroll
        for (int p = 0; p < 2; ++p) {
            const __nv_bfloat16* src = p ? Alo : Ahi;
            const uint32_t po = st + p * 8192;
#pragma unroll
            for (int i = 0; i < 2; ++i) {
                int idx = tid + i * 256;
                int row = idx >> 2, c = idx & 3;
                uint32_t dst = po + row * 64 + ((c ^ ((row >> 1) & 3)) << 4);
                CPA16(dst, src + (size_t)(m0 + row) * KDIM + kb + c * 8);
            }
        }
#pragma unroll
        for (int p = 0; p < 2; ++p) {
            const __nv_bfloat16* src = p ? Blo : Bhi;
            const uint32_t po = st + 16384 + p * 8192;
#pragma unroll
            for (int i = 0; i < 2; ++i) {
                int idx = tid + i * 256;
                int row = idx >> 2, c = idx & 3;
                uint32_t dst = po + row * 64 + ((c ^ ((row >> 1) & 3)) << 4);
                CPA16(dst, src + (size_t)(n0 + row) * KDIM + kb + c * 8);
            }
        }
        CPA_COMMIT();
    };

    load_stage(0, 0);
    load_stage(1, 1);
    load_stage(2, 2);

    const int NK = KDIM / 32;
    for (int kt = 0; kt < NK; ++kt) {
        const int s = kt & (NSTAGES - 1);
        if (kt <= NK - 3)      { CPA_WAIT2(); }
        else if (kt == NK - 2) { CPA_WAIT1(); }
        else                   { CPA_WAIT0(); }
        __syncthreads();

        const uint32_t st = sb + (uint32_t)s * STAGE_BYTES;
#pragma unroll
        for (int kh = 0; kh < 2; ++kh) {
            const int cbase = kh * 2;
            uint32_t a[2][2][4];
#pragma unroll
            for (int p = 0; p < 2; ++p) {
#pragma unroll
                for (int mf = 0; mf < 2; ++mf) {
                    int row = wm * 32 + mf * 16 + ((lane >> 3) & 1) * 8 + (lane & 7);
                    int c = cbase + ((lane >> 4) & 1);
                    uint32_t addr = st + p * 8192 + row * 64
                                  + ((c ^ ((row >> 1) & 3)) << 4);
                    LDSM4(a[p][mf], addr);
                }
            }
            uint32_t b[2][16];
#pragma unroll
            for (int p = 0; p < 2; ++p) {
#pragma unroll
                for (int nq = 0; nq < 4; ++nq) {
                    int row = wn * 64 + nq * 16 + ((lane >> 4) & 1) * 8 + (lane & 7);
                    int c = cbase + ((lane >> 3) & 1);
                    uint32_t addr = st + 16384 + p * 8192 + row * 64
                                  + ((c ^ ((row >> 1) & 3)) << 4);
                    LDSM4(&b[p][nq * 4], addr);
                }
            }
#pragma unroll
            for (int mf = 0; mf < 2; ++mf) {
#pragma unroll
                for (int nf = 0; nf < 8; ++nf) {
                    const int bi = (nf >> 1) * 4 + (nf & 1) * 2;
                    MMA_BF16(acc[mf][nf], a[0][mf], b[0][bi], b[0][bi + 1]);
                    MMA_BF16(acc[mf][nf], a[1][mf], b[0][bi], b[0][bi + 1]);
                    MMA_BF16(acc[mf][nf], a[0][mf], b[1][bi], b[1][bi + 1]);
                }
            }
        }

        if (kt + 3 < NK) load_stage(kt + 3, (kt + 3) & (NSTAGES - 1));
    }

    float scl = 1.0f, zp = 0.0f;
    if (MODE == 0) { scl = *scale_p; zp = *zp_p; }

#pragma unroll
    for (int mf = 0; mf < 2; ++mf) {
#pragma unroll
        for (int nf = 0; nf < 8; ++nf) {
            const int n = n0 + wn * 64 + nf * 8 + (lane & 3) * 2;
            const float2 bv = *(const float2*)(bias + n);
#pragma unroll
            for (int half = 0; half < 2; ++half) {
                const int m = m0 + wm * 32 + mf * 16 + (lane >> 2) + half * 8;
                float v0 = acc[mf][nf][half * 2 + 0] + bv.x;
                float v1 = acc[mf][nf][half * 2 + 1] + bv.y;
                if (MODE == 0) {
                    const int bb = m >> 11;
                    const int t = m & 2047;
                    const int which = n >> 10;
                    const int cI = n & 1023;
                    const int h = cI >> 6, d = cI & 63;
                    const size_t idx = (((size_t)(bb * NHEAD + h) * TSEQ + t) * HD + d);
                    if (which != 0) {   // fake-quant K/V
                        float q0 = fminf(fmaxf(rintf(v0 / scl + zp), 0.0f), 255.0f);
                        float q1 = fminf(fmaxf(rintf(v1 / scl + zp), 0.0f), 255.0f);
                        v0 = (q0 - zp) * scl;
                        v1 = (q1 - zp) * scl;
                    }
                    __nv_bfloat16 h0 = __float2bfloat16_rn(v0);
                    __nv_bfloat16 h1 = __float2bfloat16_rn(v1);
                    __nv_bfloat16 l0 = __float2bfloat16_rn(v0 - __bfloat162float(h0));
                    __nv_bfloat16 l1 = __float2bfloat16_rn(v1 - __bfloat162float(h1));
                    __nv_bfloat162 hv(h0, h1), lv(l0, l1);
                    if (which == 0) {
                        *(__nv_bfloat162*)(g_Qhi + idx) = hv;
                        *(__nv_bfloat162*)(g_Qlo + idx) = lv;
                    } else if (which == 1) {
                        *(__nv_bfloat162*)(g_Khi + idx) = hv;
                        *(__nv_bfloat162*)(g_Klo + idx) = lv;
                    } else {
                        *(__nv_bfloat162*)(g_Vhi + idx) = hv;
                        *(__nv_bfloat162*)(g_Vlo + idx) = lv;
                    }
                } else {
                    *(float2*)(Cout + (size_t)m * Ncols + n) = make_float2(v0, v1);
                }
            }
        }
    }
}

// ---------------------------------------------------------------------------
// Tensor-core causal flash attention (FA2-style), bf16 split-3 everywhere.
// CTA: 128 q-rows, one (b,h), 4 warps. K/V tiles of 64, double-buffered.
// SMEM rows: 64 bf16 = 128B = 8x16B units, swizzle unit' = unit ^ (row&7).
// ---------------------------------------------------------------------------
#define FS_QH 0
#define FS_QL 16384
#define FS_ST 32768
#define FS_STAGE 32768           // KH 8K | KL 8K | VH 8K | VL 8K
#define FS_TOTAL (FS_ST + 2 * FS_STAGE)   // 98304

__global__ __launch_bounds__(128, 2) void flash_mma_kernel()
{
    extern __shared__ __align__(1024) char fsm[];
    const uint32_t sb = smem_u32(fsm);
    const int qb = (TSEQ / 128 - 1) - blockIdx.x;   // long blocks first
    const int h = blockIdx.y, b = blockIdx.z;
    const int tid = threadIdx.x, warp = tid >> 5, lane = tid & 31;
    const size_t bh = (size_t)(b * NHEAD + h) * TSEQ * HD;

    const __nv_bfloat16* Qh = g_Qhi + bh + (size_t)qb * 128 * HD;
    const __nv_bfloat16* Ql = g_Qlo + bh + (size_t)qb * 128 * HD;
    const __nv_bfloat16* Kh = g_Khi + bh;
    const __nv_bfloat16* Kl = g_Klo + bh;
    const __nv_bfloat16* Vh = g_Vhi + bh;
    const __nv_bfloat16* Vl = g_Vlo + bh;

    // Q tile -> SMEM (both planes)
#pragma unroll
    for (int p = 0; p < 2; ++p) {
        const __nv_bfloat16* src = p ? Ql : Qh;
        const uint32_t base = sb + (p ? FS_QL : FS_QH);
#pragma unroll
        for (int i = 0; i < 8; ++i) {
            int idx = tid + i * 128;
            int row = idx >> 3, c = idx & 7;
            CPA16(base + row * 128 + ((c ^ (row & 7)) << 4), src + row * 64 + c * 8);
        }
    }

    auto load_tile = [&](int j, int s) {
        const uint32_t st = sb + FS_ST + (uint32_t)s * FS_STAGE;
        const __nv_bfloat16* srcs[4] = {
            Kh + (size_t)j * 64 * HD, Kl + (size_t)j * 64 * HD,
            Vh + (size_t)j * 64 * HD, Vl + (size_t)j * 64 * HD };
#pragma unroll
        for (int p = 0; p < 4; ++p) {
#pragma unroll
            for (int i = 0; i < 4; ++i) {
                int idx = tid + i * 128;
                int row = idx >> 3, c = idx & 7;
                CPA16(st + p * 8192 + row * 128 + ((c ^ (row & 7)) << 4),
                      srcs[p] + row * 64 + c * 8);
            }
        }
    };

    load_tile(0, 0);
    CPA_COMMIT();                 // group: Q + tile0
    load_tile(1, 1);
    CPA_COMMIT();                 // group: tile1

    float O[2][8][4];
#pragma unroll
    for (int mf = 0; mf < 2; ++mf)
#pragma unroll
        for (int nf = 0; nf < 8; ++nf)
#pragma unroll
            for (int e = 0; e < 4; ++e) O[mf][nf][e] = 0.0f;
    float rm[2][2], rl[2][2];
#pragma unroll
    for (int mf = 0; mf < 2; ++mf)
#pragma unroll
        for (int hf = 0; hf < 2; ++hf) { rm[mf][hf] = -1e30f; rl[mf][hf] = 0.0f; }

    const int ntiles = 2 * qb + 2;
    CPA_WAIT1();                  // Q + tile0 ready

    for (int j = 0; j < ntiles; ++j) {
        const int s = j & 1;
        __syncthreads();
        const uint32_t st = sb + FS_ST + (uint32_t)s * FS_STAGE;

        // ---- S = Q K^T (Qhi*Khi + Qlo*Khi + Qhi*Klo) ----
        float S[2][8][4];
#pragma unroll
        for (int mf = 0; mf < 2; ++mf)
#pragma unroll
            for (int nf = 0; nf < 8; ++nf)
#pragma unroll
                for (int e = 0; e < 4; ++e) S[mf][nf][e] = 0.0f;

#pragma unroll
        for (int ks = 0; ks < 4; ++ks) {
            uint32_t aQ[2][2][4];
#pragma unroll
            for (int p = 0; p < 2; ++p) {
#pragma unroll
                for (int mf = 0; mf < 2; ++mf) {
                    int row = warp * 32 + mf * 16 + ((lane >> 3) & 1) * 8 + (lane & 7);
                    int c = ks * 2 + ((lane >> 4) & 1);
                    LDSM4(aQ[p][mf], sb + (p ? FS_QL : FS_QH) + row * 128
                                     + ((c ^ (row & 7)) << 4));
                }
            }
            uint32_t bK[2][4][4];
#pragma unroll
            for (int p = 0; p < 2; ++p) {
#pragma unroll
                for (int kg = 0; kg < 4; ++kg) {
                    int row = kg * 16 + ((lane >> 4) & 1) * 8 + (lane & 7);
                    int c = ks * 2 + ((lane >> 3) & 1);
                    LDSM4(bK[p][kg], st + p * 8192 + row * 128
                                     + ((c ^ (row & 7)) << 4));
                }
            }
#pragma unroll
            for (int mf = 0; mf < 2; ++mf) {
#pragma unroll
                for (int nf = 0; nf < 8; ++nf) {
                    const int kg = nf >> 1, o = (nf & 1) * 2;
                    MMA_BF16(S[mf][nf], aQ[0][mf], bK[0][kg][o], bK[0][kg][o + 1]);
                    MMA_BF16(S[mf][nf], aQ[1][mf], bK[0][kg][o], bK[0][kg][o + 1]);
                    MMA_BF16(S[mf][nf], aQ[0][mf], bK[1][kg][o], bK[1][kg][o + 1]);
                }
            }
        }

        // ---- scale + causal mask ----
        const bool maskT = (j >= 2 * qb);
#pragma unroll
        for (int mf = 0; mf < 2; ++mf)
#pragma unroll
            for (int nf = 0; nf < 8; ++nf)
#pragma unroll
                for (int e = 0; e < 4; ++e) {
                    float sv = S[mf][nf][e] * 0.125f;
                    if (maskT) {
                        const int key = j * 64 + nf * 8 + (lane & 3) * 2 + (e & 1);
                        const int rowg = qb * 128 + warp * 32 + mf * 16
                                       + (lane >> 2) + (e >> 1) * 8;
                        if (key > rowg) sv = -1e30f;
                    }
                    S[mf][nf][e] = sv;
                }

        // ---- online softmax per (mf, half-row) ----
#pragma unroll
        for (int mf = 0; mf < 2; ++mf) {
#pragma unroll
            for (int hf = 0; hf < 2; ++hf) {
                float mx = -1e30f;
#pragma unroll
                for (int nf = 0; nf < 8; ++nf)
                    mx = fmaxf(mx, fmaxf(S[mf][nf][hf * 2], S[mf][nf][hf * 2 + 1]));
                mx = fmaxf(mx, __shfl_xor_sync(0xFFFFFFFFu, mx, 1));
                mx = fmaxf(mx, __shfl_xor_sync(0xFFFFFFFFu, mx, 2));
                const float mnew = fmaxf(rm[mf][hf], mx);
                const float corr = __expf(rm[mf][hf] - mnew);
                rm[mf][hf] = mnew;
                float ps = 0.0f;
#pragma unroll
                for (int nf = 0; nf < 8; ++nf) {
                    float p0 = __expf(S[mf][nf][hf * 2 + 0] - mnew);
                    float p1 = __expf(S[mf][nf][hf * 2 + 1] - mnew);
                    S[mf][nf][hf * 2 + 0] = p0;
                    S[mf][nf][hf * 2 + 1] = p1;
                    ps += p0 + p1;
                }
                ps += __shfl_xor_sync(0xFFFFFFFFu, ps, 1);
                ps += __shfl_xor_sync(0xFFFFFFFFu, ps, 2);
                rl[mf][hf] = rl[mf][hf] * corr + ps;
#pragma unroll
                for (int nf = 0; nf < 8; ++nf) {
                    O[mf][nf][hf * 2 + 0] *= corr;
                    O[mf][nf][hf * 2 + 1] *= corr;
                }
            }
        }

        // ---- O += P V (Phi*Vhi + Plo*Vhi + Phi*Vlo) ----
#pragma unroll
        for (int kc = 0; kc < 4; ++kc) {
            uint32_t aP[2][2][4];
#pragma unroll
            for (int mf = 0; mf < 2; ++mf) {
#pragma unroll
                for (int e = 0; e < 2; ++e) {        // e: nf 2kc / 2kc+1
                    const int nf = 2 * kc + e;
#pragma unroll
                    for (int hf = 0; hf < 2; ++hf) {
                        float x = S[mf][nf][hf * 2 + 0];
                        float y = S[mf][nf][hf * 2 + 1];
                        __nv_bfloat16 hx = __float2bfloat16_rn(x);
                        __nv_bfloat16 hy = __float2bfloat16_rn(y);
                        __nv_bfloat162 hv(hx, hy);
                        __nv_bfloat162 lv(
                            __float2bfloat16_rn(x - __bfloat162float(hx)),
                            __float2bfloat16_rn(y - __bfloat162float(hy)));
                        aP[0][mf][e * 2 + hf] = *(uint32_t*)&hv;
                        aP[1][mf][e * 2 + hf] = *(uint32_t*)&lv;
                    }
                }
            }
            uint32_t bV[2][4][4];
#pragma unroll
            for (int p = 0; p < 2; ++p) {
#pragma unroll
                for (int dg = 0; dg < 4; ++dg) {
                    int row = kc * 16 + ((lane >> 3) & 1) * 8 + (lane & 7);
                    int c = dg * 2 + ((lane >> 4) & 1);
                    LDSM4T(bV[p][dg], st + (2 + p) * 8192 + row * 128
                                      + ((c ^ (row & 7)) << 4));
                }
            }
#pragma unroll
            for (int mf = 0; mf < 2; ++mf) {
#pragma unroll
                for (int nf = 0; nf < 8; ++nf) {
                    const int dg = nf >> 1, o = (nf & 1) * 2;
                    MMA_BF16(O[mf][nf], aP[0][mf], bV[0][dg][o], bV[0][dg][o + 1]);
                    MMA_BF16(O[mf][nf], aP[1][mf], bV[0][dg][o], bV[0][dg][o + 1]);
                    MMA_BF16(O[mf][nf], aP[0][mf], bV[1][dg][o], bV[1][dg][o + 1]);
                }
            }
        }

        __syncthreads();
        if (j + 2 < ntiles) { load_tile(j + 2, s); CPA_COMMIT(); }
        if (j + 1 < ntiles) {
            if (j + 2 < ntiles) { CPA_WAIT1(); } else { CPA_WAIT0(); }
        }
    }

    // ---- epilogue: normalize, split to bf16 hi/lo, write [B,T,C] ----
#pragma unroll
    for (int mf = 0; mf < 2; ++mf) {
#pragma unroll
        for (int hf = 0; hf < 2; ++hf) {
            const float inv = 1.0f / rl[mf][hf];
            const int row = qb * 128 + warp * 32 + mf * 16 + (lane >> 2) + hf * 8;
            const size_t ob = ((size_t)(b * TSEQ) + row) * CDIM + h * 64;
#pragma unroll
            for (int nf = 0; nf < 8; ++nf) {
                const int d = nf * 8 + (lane & 3) * 2;
                float v0 = O[mf][nf][hf * 2 + 0] * inv;
                float v1 = O[mf][nf][hf * 2 + 1] * inv;
                __nv_bfloat16 h0 = __float2bfloat16_rn(v0);
                __nv_bfloat16 h1 = __float2bfloat16_rn(v1);
                __nv_bfloat162 hv(h0, h1);
                __nv_bfloat162 lv(
                    __float2bfloat16_rn(v0 - __bfloat162float(h0)),
                    __float2bfloat16_rn(v1 - __bfloat162float(h1)));
                *(__nv_bfloat162*)(g_Ohi + ob + d) = hv;
                *(__nv_bfloat162*)(g_Olo + ob + d) = lv;
            }
        }
    }
}

// ---------------------------------------------------------------------------
// Launch
// ---------------------------------------------------------------------------
extern "C" void kernel_launch(void* const* d_in, const int* in_sizes, int n_in,
                              void* d_out, int out_size)
{
    const float* hidden   = (const float*)d_in[0];
    const float* W_attn   = (const float*)d_in[1];
    const float* b_attn   = (const float*)d_in[2];
    const float* W_proj   = (const float*)d_in[3];
    const float* b_proj   = (const float*)d_in[4];
    const float* kv_scale = (const float*)d_in[5];
    const float* kv_zp    = (const float*)d_in[6];
    float* out = (float*)d_out;

    cudaFuncSetAttribute(mma_gemm_kernel<0>,
                         cudaFuncAttributeMaxDynamicSharedMemorySize, SMEM_DYN);
    cudaFuncSetAttribute(mma_gemm_kernel<1>,
                         cudaFuncAttributeMaxDynamicSharedMemorySize, SMEM_DYN);
    cudaFuncSetAttribute(flash_mma_kernel,
                         cudaFuncAttributeMaxDynamicSharedMemorySize, FS_TOTAL);

    __nv_bfloat16 *Xhi, *Xlo, *WaThi, *WaTlo, *WpThi, *WpTlo, *Ohi, *Olo;
    cudaGetSymbolAddress((void**)&Xhi, g_Xhi);
    cudaGetSymbolAddress((void**)&Xlo, g_Xlo);
    cudaGetSymbolAddress((void**)&WaThi, g_WaThi);
    cudaGetSymbolAddress((void**)&WaTlo, g_WaTlo);
    cudaGetSymbolAddress((void**)&WpThi, g_WpThi);
    cudaGetSymbolAddress((void**)&WpTlo, g_WpTlo);
    cudaGetSymbolAddress((void**)&Ohi, g_Ohi);
    cudaGetSymbolAddress((void**)&Olo, g_Olo);

    // Prep
    split_kernel<<<1024, 256>>>(hidden, Xhi, Xlo, MROWS * CDIM / 4);
    transpose_split_kernel<<<dim3(NQKV / 32, CDIM / 32), 256>>>(W_attn, WaThi, WaTlo, CDIM, NQKV);
    transpose_split_kernel<<<dim3(CDIM / 32, CDIM / 32), 256>>>(W_proj, WpThi, WpTlo, CDIM, CDIM);

    // QKV GEMM + bias + fake-quant + bf16 hi/lo scatter
    mma_gemm_kernel<0><<<dim3(NQKV / 128, MROWS / 128), 256, SMEM_DYN>>>(
        Xhi, Xlo, WaThi, WaTlo, b_attn, NQKV, kv_scale, kv_zp, nullptr);

    // Tensor-core causal flash attention
    flash_mma_kernel<<<dim3(TSEQ / 128, NHEAD, BATCH), 128, FS_TOTAL>>>();

    // Output projection
    mma_gemm_kernel<1><<<dim3(CDIM / 128, MROWS / 128), 256, SMEM_DYN>>>(
        Ohi, Olo, WpThi, WpTlo, b_proj, CDIM, nullptr, nullptr, out);
}